// round 3
// baseline (speedup 1.0000x reference)
#include <cuda_runtime.h>
#include <cuda_bf16.h>

// Problem constants
#define O_CH   256
#define C_IN   128
#define K_H    24
#define N_IN   24
#define N_OUT  24
#define KS     5

// wH elements: O*N_in*C*N_out = 256*24*128*24
#define WH_ELEMS  18874368
// wRn elements: O*N_out*125
#define WRN_ELEMS 768000

// nearest-neighbor index on SO(3) grid, per (a,b) pair
__device__ int g_nn[N_IN * N_OUT];

// ---------------------------------------------------------------------------
// Kernel 1: nn[a,b] = argmax_kh <out_H[b]^T @ in_H[a], grid_H[kh]>_F
// ---------------------------------------------------------------------------
__global__ void nn_kernel(const float* __restrict__ in_H,
                          const float* __restrict__ out_H,
                          const float* __restrict__ grid_H) {
    __shared__ float si[N_IN * 9];
    __shared__ float so[N_OUT * 9];
    __shared__ float sg[K_H * 9];
    int t = threadIdx.x;
    if (t < N_IN * 9)  si[t] = in_H[t];
    if (t < N_OUT * 9) so[t] = out_H[t];
    if (t < K_H * 9)   sg[t] = grid_H[t];
    __syncthreads();

    if (t < N_IN * N_OUT) {
        int a = t / N_OUT;
        int b = t % N_OUT;
        const float* A = si + a * 9;   // in_H[a][j][k]
        const float* B = so + b * 9;   // out_H[b][j][i]
        // P[i][k] = sum_j out_H[b][j][i] * in_H[a][j][k]   (= out_H[b]^T @ in_H[a])
        float P[9];
        #pragma unroll
        for (int i = 0; i < 3; i++)
            #pragma unroll
            for (int k = 0; k < 3; k++) {
                float s = 0.f;
                #pragma unroll
                for (int j = 0; j < 3; j++)
                    s += B[j * 3 + i] * A[j * 3 + k];
                P[i * 3 + k] = s;
            }
        float best = -1e30f;
        int bi = 0;
        for (int kh = 0; kh < K_H; kh++) {
            const float* G = sg + kh * 9;
            float s = 0.f;
            #pragma unroll
            for (int e = 0; e < 9; e++) s += P[e] * G[e];
            if (s > best) { best = s; bi = kh; }  // strict > : first-max wins (JAX argmax)
        }
        g_nn[t] = bi;
    }
}

// ---------------------------------------------------------------------------
// Kernel 2: wH[o,a,c,b] = weight_H[o,c,nn[a,b]]
// grid: (o = 0..255, aQuarter = 0..3); each block stages weight_H[o] (12 KB)
// in shared, then writes 6 a-slices with coalesced float4 stores.
// 384 threads: 6*128*6 = 4608 float4 per block = exactly 12 iters/thread.
// ---------------------------------------------------------------------------
__global__ void __launch_bounds__(384)
wh_kernel(const float* __restrict__ weight_H,
          float* __restrict__ out) {
    __shared__ float sw[C_IN * K_H];        // 3072 floats = 12 KB
    __shared__ int   snn[N_IN * N_OUT];     // 576 ints

    int o = blockIdx.x;
    // stage weight_H[o] (coalesced float4)
    const float4* wsrc = (const float4*)(weight_H + (size_t)o * C_IN * K_H);
    float4* sw4 = (float4*)sw;
    for (int i = threadIdx.x; i < (C_IN * K_H) / 4; i += blockDim.x)
        sw4[i] = wsrc[i];
    for (int i = threadIdx.x; i < N_IN * N_OUT; i += blockDim.x)
        snn[i] = g_nn[i];
    __syncthreads();

    int aBase = blockIdx.y * 6;             // 6 a-values per block

    // Decompose threadIdx.x once: v = ((a_local*128 + c)*6 + g)
    int g0i = threadIdx.x % 6;
    int ac0 = threadIdx.x / 6;              // 0..63 (384/6 = 64 exact)
    // Each iteration advances v by 384 = 64*6: g stays fixed, ac += 64.
    float4* dst4 = (float4*)out;

    for (int ac = ac0; ac < 6 * C_IN; ac += 64) {
        int c = ac & (C_IN - 1);
        int a = aBase + (ac >> 7);
        const int*   nn = snn + a * N_OUT + g0i * 4;
        const float* wr = sw + c * K_H;
        float4 r;
        r.x = wr[nn[0]];
        r.y = wr[nn[1]];
        r.z = wr[nn[2]];
        r.w = wr[nn[3]];
        size_t outIdx = ((size_t)(o * N_IN + a) * C_IN + c) * (N_OUT / 4) + g0i;
        dst4[outIdx] = r;
    }
}

// ---------------------------------------------------------------------------
// Kernel 3: wRn[o,b,z,y,x] = trilinear(weight_Rn[o], out_H[b]^T @ grid_Rn[:,z,y,x])
// align_corners=True, zero padding, exact reference tap semantics.
// one thread per output element; writes coalesced.
// ---------------------------------------------------------------------------
__global__ void wrn_kernel(const float* __restrict__ out_H,
                           const float* __restrict__ grid_Rn,
                           const float* __restrict__ weight_Rn,
                           float* __restrict__ out) {
    int idx = blockIdx.x * blockDim.x + threadIdx.x;
    if (idx >= WRN_ELEMS) return;

    int s  = idx % (KS * KS * KS);          // spatial position (z*25+y*5+x)
    int ob = idx / (KS * KS * KS);
    int b  = ob % N_OUT;
    int o  = ob / N_OUT;

    // grid coordinates (3 channels, z-major spatial)
    float g0 = __ldg(grid_Rn + 0 * 125 + s);
    float g1 = __ldg(grid_Rn + 1 * 125 + s);
    float g2 = __ldg(grid_Rn + 2 * 125 + s);

    // rotated coords: c_i = sum_j out_H[b][j][i] * g_j   (out_inv = out_H^T)
    const float* R = out_H + b * 9;
    float r00 = __ldg(R + 0), r01 = __ldg(R + 1), r02 = __ldg(R + 2);
    float r10 = __ldg(R + 3), r11 = __ldg(R + 4), r12 = __ldg(R + 5);
    float r20 = __ldg(R + 6), r21 = __ldg(R + 7), r22 = __ldg(R + 8);
    float c0 = r00 * g0 + r10 * g1 + r20 * g2;
    float c1 = r01 * g0 + r11 * g1 + r21 * g2;
    float c2 = r02 * g0 + r12 * g1 + r22 * g2;

    // to voxel coords (align_corners=True, size 5 -> scale (5-1)/2 = 2)
    float cz = (c0 + 1.0f) * 2.0f;
    float cy = (c1 + 1.0f) * 2.0f;
    float cx = (c2 + 1.0f) * 2.0f;
    float fz0 = floorf(cz), fy0 = floorf(cy), fx0 = floorf(cx);
    float fz = cz - fz0, fy = cy - fy0, fx = cx - fx0;
    int z0 = (int)fz0, y0 = (int)fy0, x0 = (int)fx0;

    const float* vol = weight_Rn + (size_t)o * 125;

    auto tap = [&](int iz, int iy, int ix) -> float {
        bool valid = (iz >= 0) & (iz < KS) & (iy >= 0) & (iy < KS) &
                     (ix >= 0) & (ix < KS);
        int zi = min(max(iz, 0), KS - 1);
        int yi = min(max(iy, 0), KS - 1);
        int xi = min(max(ix, 0), KS - 1);
        float v = __ldg(vol + zi * 25 + yi * 5 + xi);
        return valid ? v : 0.0f;
    };

    float w000 = (1.f - fz) * (1.f - fy) * (1.f - fx);
    float w001 = (1.f - fz) * (1.f - fy) * fx;
    float w010 = (1.f - fz) * fy * (1.f - fx);
    float w011 = (1.f - fz) * fy * fx;
    float w100 = fz * (1.f - fy) * (1.f - fx);
    float w101 = fz * (1.f - fy) * fx;
    float w110 = fz * fy * (1.f - fx);
    float w111 = fz * fy * fx;

    float r = tap(z0,     y0,     x0)     * w000
            + tap(z0,     y0,     x0 + 1) * w001
            + tap(z0,     y0 + 1, x0)     * w010
            + tap(z0,     y0 + 1, x0 + 1) * w011
            + tap(z0 + 1, y0,     x0)     * w100
            + tap(z0 + 1, y0,     x0 + 1) * w101
            + tap(z0 + 1, y0 + 1, x0)     * w110
            + tap(z0 + 1, y0 + 1, x0 + 1) * w111;

    out[idx] = r;
}

// ---------------------------------------------------------------------------
extern "C" void kernel_launch(void* const* d_in, const int* in_sizes, int n_in,
                              void* d_out, int out_size) {
    const float* in_H      = (const float*)d_in[0];   // [24,3,3]
    const float* out_H     = (const float*)d_in[1];   // [24,3,3]
    const float* grid_H    = (const float*)d_in[2];   // [24,3,3]
    const float* grid_Rn   = (const float*)d_in[3];   // [3,5,5,5]
    const float* weight_H  = (const float*)d_in[4];   // [256,128,24]
    const float* weight_Rn = (const float*)d_in[5];   // [256,1,5,5,5]
    float* out = (float*)d_out;

    nn_kernel<<<1, 576>>>(in_H, out_H, grid_H);
    wh_kernel<<<dim3(O_CH, 4), 384>>>(weight_H, out);
    wrn_kernel<<<(WRN_ELEMS + 255) / 256, 256>>>(out_H, grid_Rn, weight_Rn,
                                                 out + WH_ELEMS);
}